// round 11
// baseline (speedup 1.0000x reference)
#include <cuda_runtime.h>
#include <cstdint>
#include <math.h>

#define BATCH 16
#define CCH   256
#define LSEQ  2048
#define BM    64
#define BN    64
#define NTILES 32
#define NTHREADS 512   // 16 warps

#define QS_STRIDE 260          // bank 4g+tig
#define KV_STRIDE 72           // bank 8tig+g (S-B) / 8g+tig (PV-B)
#define SS_STRIDE 68           // bank 4g+tig
#define SBUF (BM * SS_STRIDE)  // 4352 floats per partial-S buffer

#define QS_FLOATS (BM * QS_STRIDE)    // 16640
#define KV_FLOATS (CCH * KV_STRIDE)   // 18432
#define SS_FLOATS (4 * SBUF)          // 17408 (4 K-split partials; buf0 reused as P)
#define SMEM_FLOATS (QS_FLOATS + KV_FLOATS + SS_FLOATS + 3 * 64)
#define SMEM_BYTES  (SMEM_FLOATS * 4) // 211,712 B < 232,448

__device__ __forceinline__ unsigned tf32b(float x) {
    unsigned u; asm("cvt.rna.tf32.f32 %0, %1;" : "=r"(u) : "f"(x));
    return u;
}
__device__ __forceinline__ float to_tf32(float x) { return __uint_as_float(tf32b(x)); }

__device__ __forceinline__ void mma_tf32(float d[4], const float a[4], const float b[2]) {
    const unsigned* A = reinterpret_cast<const unsigned*>(a);
    const unsigned* B = reinterpret_cast<const unsigned*>(b);
    asm volatile(
        "mma.sync.aligned.m16n8k8.row.col.f32.tf32.tf32.f32 "
        "{%0,%1,%2,%3}, {%4,%5,%6,%7}, {%8,%9}, {%0,%1,%2,%3};\n"
        : "+f"(d[0]), "+f"(d[1]), "+f"(d[2]), "+f"(d[3])
        : "r"(A[0]), "r"(A[1]), "r"(A[2]), "r"(A[3]), "r"(B[0]), "r"(B[1]));
}

__global__ void __launch_bounds__(NTHREADS, 1)
attn_ks_kernel(const float* __restrict__ Q, const float* __restrict__ K,
               const float* __restrict__ V, const float* __restrict__ Mask,
               float* __restrict__ Out) {
    extern __shared__ float smem[];
    float* Qs    = smem;                  // [64][260] (l,c) tf32, *1/16
    float* KVs   = Qs + QS_FLOATS;        // [256][72] (c,m): K then V
    float* Ss    = KVs + KV_FLOATS;       // 4 x [64][68]: S partials; buf0 -> P
    float* maskT = Ss + SS_FLOATS;        // [64]
    float* lmT   = maskT + 64;            // [64]
    float* Drow  = lmT + 64;              // [64]

    const int tid = threadIdx.x, w = tid >> 5, lane = tid & 31;
    const int g = lane >> 2, tig = lane & 3;
    const int b = blockIdx.y, l0 = blockIdx.x * BM;

    const float* Qb = Q + (size_t)b * CCH * LSEQ;
    const float* Kb = K + (size_t)b * CCH * LSEQ;
    const float* Vb = V + (size_t)b * CCH * LSEQ;
    const float* Mb = Mask + (size_t)b * LSEQ;

    // ---- stage Q once: Qs[l][c] = tf32(Q[b][c][l0+l]/16) ----
    {
        const float s16 = 0.0625f;
        #pragma unroll
        for (int i = 0; i < 8; i++) {
            int idx = i * NTHREADS + tid;   // 0..4095
            int c = idx >> 4, j = idx & 15;
            float4 v = *reinterpret_cast<const float4*>(Qb + (size_t)c * LSEQ + l0 + 4 * j);
            Qs[(4 * j + 0) * QS_STRIDE + c] = to_tf32(v.x * s16);
            Qs[(4 * j + 1) * QS_STRIDE + c] = to_tf32(v.y * s16);
            Qs[(4 * j + 2) * QS_STRIDE + c] = to_tf32(v.z * s16);
            Qs[(4 * j + 3) * QS_STRIDE + c] = to_tf32(v.w * s16);
        }
    }

    // S-GEMM decomposition: 2x2 spatial x 4 K-quarters, warp tile 32x32
    const int kq = w & 3;              // K quarter: k in [64*kq, 64*kq+64)
    const int R0 = 32 * ((w >> 2) & 1);
    const int C0 = 32 * (w >> 3);
    const int kbase = 64 * kq;
    float* Sb = Ss + kq * SBUF;

    // PV decomposition: warp tile 32 rows x 32 channels (2x8 grid)
    const int Rp = 32 * (w & 1);
    const int Cb = 32 * (w >> 1);

    float O[2][4][4];
    #pragma unroll
    for (int mt = 0; mt < 2; mt++)
        #pragma unroll
        for (int nt = 0; nt < 4; nt++)
            #pragma unroll
            for (int r = 0; r < 4; r++) O[mt][nt][r] = 0.0f;

    const int sr = tid >> 3;        // softmax row
    const int cq = (tid & 7) * 8;   // softmax col base (8 cols)
    float den = 0.0f;

    __syncthreads();

    for (int t = 0; t < NTILES; t++) {
        const int m0 = t * BN;

        // ---- stage K tile ----
        #pragma unroll
        for (int i = 0; i < 8; i++) {
            int idx = i * NTHREADS + tid;   // 0..4095
            int c = idx >> 4, j = idx & 15;
            float4 v = *reinterpret_cast<const float4*>(Kb + (size_t)c * LSEQ + m0 + 4 * j);
            v.x = to_tf32(v.x); v.y = to_tf32(v.y); v.z = to_tf32(v.z); v.w = to_tf32(v.w);
            *reinterpret_cast<float4*>(&KVs[c * KV_STRIDE + 4 * j]) = v;
        }
        if (tid < 64) {
            float mk = Mb[m0 + tid];
            maskT[tid] = mk;
            lmT[tid] = __logf(mk + 1e-9f);
        }
        __syncthreads();

        // ---- S partial: warp tile 32x32, K-quarter of 64 ----
        {
            float sacc[2][4][4];
            #pragma unroll
            for (int mt = 0; mt < 2; mt++)
                #pragma unroll
                for (int nt = 0; nt < 4; nt++)
                    #pragma unroll
                    for (int r = 0; r < 4; r++) sacc[mt][nt][r] = 0.0f;

            const float* q0 = &Qs[(R0 + g) * QS_STRIDE];
            #pragma unroll
            for (int ks = 0; ks < 8; ks++) {
                const int k0 = kbase + 8 * ks;
                float a0[4], a1[4];
                a0[0] = q0[k0 + tig];
                a0[1] = q0[8 * QS_STRIDE + k0 + tig];
                a0[2] = q0[k0 + tig + 4];
                a0[3] = q0[8 * QS_STRIDE + k0 + tig + 4];
                a1[0] = q0[16 * QS_STRIDE + k0 + tig];
                a1[1] = q0[24 * QS_STRIDE + k0 + tig];
                a1[2] = q0[16 * QS_STRIDE + k0 + tig + 4];
                a1[3] = q0[24 * QS_STRIDE + k0 + tig + 4];
                const float* bp = &KVs[(k0 + tig) * KV_STRIDE + C0 + g];
                #pragma unroll
                for (int nt = 0; nt < 4; nt++) {
                    float bb[2] = { bp[8 * nt], bp[4 * KV_STRIDE + 8 * nt] };
                    mma_tf32(sacc[0][nt], a0, bb);
                    mma_tf32(sacc[1][nt], a1, bb);
                }
            }
            #pragma unroll
            for (int mt = 0; mt < 2; mt++)
                #pragma unroll
                for (int nt = 0; nt < 4; nt++) {
                    int row = R0 + 16 * mt + g;
                    int col = C0 + 8 * nt + 2 * tig;
                    *reinterpret_cast<float2*>(&Sb[row * SS_STRIDE + col]) =
                        make_float2(sacc[mt][nt][0], sacc[mt][nt][1]);
                    *reinterpret_cast<float2*>(&Sb[(row + 8) * SS_STRIDE + col]) =
                        make_float2(sacc[mt][nt][2], sacc[mt][nt][3]);
                }
        }
        __syncthreads();

        // ---- stage V (overwrites K; LDGs overlap softmax below) ----
        #pragma unroll
        for (int i = 0; i < 8; i++) {
            int idx = i * NTHREADS + tid;
            int c = idx >> 4, j = idx & 15;
            float4 v = *reinterpret_cast<const float4*>(Vb + (size_t)c * LSEQ + m0 + 4 * j);
            v.x = to_tf32(v.x); v.y = to_tf32(v.y); v.z = to_tf32(v.z); v.w = to_tf32(v.w);
            *reinterpret_cast<float4*>(&KVs[c * KV_STRIDE + 4 * j]) = v;
        }

        // ---- softmax (no max-subtraction; logits bounded ~6): sum 4 partials ----
        {
            float* s0 = &Ss[sr * SS_STRIDE + cq];
            const float* lmp = &lmT[cq];
            const float* mp  = &maskT[cq];
            #pragma unroll
            for (int j = 0; j < 8; j++) {
                float s = s0[j] + s0[j + SBUF] + s0[j + 2 * SBUF] + s0[j + 3 * SBUF] + lmp[j];
                float e = __expf(s);
                den += e;
                s0[j] = __uint_as_float(tf32b(e * mp[j]));   // P into buf0
            }
        }
        __syncthreads();

        // ---- O += V * P^T, warp tile 32 rows x 32 channels, K-dim 64 ----
        {
            const float* p0 = &Ss[(Rp + g) * SS_STRIDE];
            #pragma unroll
            for (int ks = 0; ks < 8; ks++) {
                const int k0 = 8 * ks;
                float a0[4], a1[4];
                a0[0] = p0[k0 + tig];
                a0[1] = p0[8 * SS_STRIDE + k0 + tig];
                a0[2] = p0[k0 + tig + 4];
                a0[3] = p0[8 * SS_STRIDE + k0 + tig + 4];
                a1[0] = p0[16 * SS_STRIDE + k0 + tig];
                a1[1] = p0[24 * SS_STRIDE + k0 + tig];
                a1[2] = p0[16 * SS_STRIDE + k0 + tig + 4];
                a1[3] = p0[24 * SS_STRIDE + k0 + tig + 4];
                #pragma unroll
                for (int nt = 0; nt < 4; nt++) {
                    const float* vp = &KVs[(Cb + 8 * nt + g) * KV_STRIDE + k0 + tig];
                    float bb[2] = { vp[0], vp[4] };
                    mma_tf32(O[0][nt], a0, bb);
                    mma_tf32(O[1][nt], a1, bb);
                }
            }
        }
        __syncthreads();
    }

    // ---- reduce denominators (8 threads per row, adjacent lanes) ----
    den += __shfl_xor_sync(0xffffffffu, den, 1);
    den += __shfl_xor_sync(0xffffffffu, den, 2);
    den += __shfl_xor_sync(0xffffffffu, den, 4);
    if ((tid & 7) == 0) Drow[sr] = den;
    __syncthreads();

    // ---- epilogue: O/den, transpose via smem (reuse Q/KV area), coalesced stores ----
    float* T = smem + w * 1056;   // 32 ch x 32 l, stride 33
    #pragma unroll
    for (int mt = 0; mt < 2; mt++) {
        float inv0 = 1.0f / Drow[Rp + 16 * mt + g];
        float inv1 = 1.0f / Drow[Rp + 16 * mt + 8 + g];
        #pragma unroll
        for (int nt = 0; nt < 4; nt++) {
            int c2 = 8 * nt + 2 * tig;
            int rl = 16 * mt + g;
            T[(c2    ) * 33 + rl    ] = O[mt][nt][0] * inv0;
            T[(c2 + 1) * 33 + rl    ] = O[mt][nt][1] * inv0;
            T[(c2    ) * 33 + rl + 8] = O[mt][nt][2] * inv1;
            T[(c2 + 1) * 33 + rl + 8] = O[mt][nt][3] * inv1;
        }
    }
    __syncwarp();
    float* outw = Out + ((size_t)b * CCH + Cb) * LSEQ + l0 + Rp;
    #pragma unroll 4
    for (int cl = 0; cl < 32; cl++)
        outw[(size_t)cl * LSEQ + lane] = T[cl * 33 + lane];
}

extern "C" void kernel_launch(void* const* d_in, const int* in_sizes, int n_in,
                              void* d_out, int out_size) {
    (void)in_sizes; (void)n_in; (void)out_size;
    const float* Q = (const float*)d_in[0];
    const float* K = (const float*)d_in[1];
    const float* V = (const float*)d_in[2];
    const float* M = (const float*)d_in[3];
    float* O = (float*)d_out;

    cudaFuncSetAttribute(attn_ks_kernel,
                         cudaFuncAttributeMaxDynamicSharedMemorySize, SMEM_BYTES);
    dim3 grid(LSEQ / BM, BATCH);   // 32 x 16 = 512 CTAs
    attn_ks_kernel<<<grid, NTHREADS, SMEM_BYTES>>>(Q, K, V, M, O);
}